// round 1
// baseline (speedup 1.0000x reference)
#include <cuda_runtime.h>
#include <math.h>

// Problem constants (fixed by reference)
#define BATCH 512
#define NE    32      // electrons
#define NUP   16
#define NA    8       // atoms
#define DF    32      // dist features
#define WH    16      // w-MLP hidden
#define KD    8       // kernel dim
#define ED    16      // embed dim
#define NL    2       // layers

// ---- shared memory layout (floats) ----
#define OFF_W1   0                      // [2][3][32][16] = 3072
#define OFF_B1   (OFF_W1 + 3072)        // [2][3][16] = 96
#define OFF_W2   (OFF_B1 + 96)          // [2][3][16][8] = 768
#define OFF_B2   (OFF_W2 + 768)         // [2][3][8] = 48
#define OFF_HW   (OFF_B2 + 48)          // [2][16][8] = 256
#define OFF_HB   (OFF_HW + 256)         // [2][8] = 16
#define OFF_GW   (OFF_HB + 16)          // [2][8][16] = 256
#define OFF_GB   (OFF_GW + 256)         // [2][16] = 32
#define OFF_ORB  (OFF_GB + 32)          // [16]
#define OFF_XE   (OFF_ORB + 16)         // [2][16] = 32
#define OFF_Y    (OFF_XE + 32)          // [8][8] = 64
#define OFF_WF   (OFF_Y + 64)           // [2][32][32][8] = 16384
#define OFF_ZN   (OFF_WF + 16384)       // [2][32][8] = 512
#define OFF_X    (OFF_ZN + 512)         // [32][16] = 512
#define OFF_HX   (OFF_X + 512)          // [32][8] = 256
#define OFF_Z    (OFF_HX + 256)         // [32][8] = 256
#define OFF_RED  (OFF_Z + 256)          // [1]
#define SMEM_FLOATS (OFF_RED + 4)       // pad

__device__ __forceinline__ float sspf(float x) {
    // softplus(x) - ln2, numerically stable, fast intrinsics
    float t = __expf(-fabsf(x));
    return fmaxf(x, 0.f) + __logf(1.f + t) - 0.6931471805599453f;
}

__global__ void __launch_bounds__(256, 2)
jastrow_kernel(const float* __restrict__ ee,   // [B,32,32,32]
               const float* __restrict__ en,   // [B,32,8,32]
               const float* __restrict__ Xemb, // [2,16]
               const float* __restrict__ Yv,   // [8,8]
               const float* __restrict__ wW1,  // [2,3,32,16]
               const float* __restrict__ wb1,  // [2,3,16]
               const float* __restrict__ wW2,  // [2,3,16,8]
               const float* __restrict__ wb2,  // [2,3,8]
               const float* __restrict__ hW,   // [2,16,8]
               const float* __restrict__ hb,   // [2,8]
               const float* __restrict__ gW,   // [2,8,16]
               const float* __restrict__ gb,   // [2,16]
               const float* __restrict__ orbW, // [16]
               float* __restrict__ out)        // [B]
{
    extern __shared__ float s[];
    const int tid  = threadIdx.x;
    const int lane = tid & 31;
    const int warp = tid >> 5;
    const int b    = blockIdx.x;

    // ---- load all weights into shared ----
    for (int t = tid; t < 3072; t += 256) s[OFF_W1 + t] = wW1[t];
    for (int t = tid; t < 96;   t += 256) s[OFF_B1 + t] = wb1[t];
    for (int t = tid; t < 768;  t += 256) s[OFF_W2 + t] = wW2[t];
    for (int t = tid; t < 48;   t += 256) s[OFF_B2 + t] = wb2[t];
    for (int t = tid; t < 256;  t += 256) s[OFF_HW + t] = hW[t];
    for (int t = tid; t < 16;   t += 256) s[OFF_HB + t] = hb[t];
    for (int t = tid; t < 256;  t += 256) s[OFF_GW + t] = gW[t];
    for (int t = tid; t < 32;   t += 256) s[OFF_GB + t] = gb[t];
    for (int t = tid; t < 16;   t += 256) s[OFF_ORB + t] = orbW[t];
    for (int t = tid; t < 32;   t += 256) s[OFF_XE + t] = Xemb[t];
    for (int t = tid; t < 64;   t += 256) s[OFF_Y + t]  = Yv[t];
    for (int t = tid; t < 512;  t += 256) s[OFF_ZN + t] = 0.f;   // z_nuc accum
    if (tid == 0) s[OFF_RED] = 0.f;
    __syncthreads();

    // ================= Phase 1: per-edge filter MLPs =================
    // 40 warp-tasks of 32 edges each, channel-uniform per task:
    //  tk 0..7  : up-up    (c=0, mask diag)
    //  tk 8..15 : up-down  (c=1)
    //  tk 16..23: down-up  (c=1)
    //  tk 24..31: down-down(c=0, mask diag)
    //  tk 32..39: nuclear  (c=2)
    for (int tk = warp; tk < 40; tk += 8) {
        int c, i, jm;
        float mask = 1.f;
        const float* ebase;
        bool isnuc = (tk >= 32);
        if (!isnuc) {
            int g = tk >> 3;                       // 0..3
            int q = ((tk & 7) << 5) + lane;        // 0..255
            i  = ((g >> 1) << 4) + (q >> 4);
            jm = (((g == 1) | (g == 3)) ? 16 : 0) + (q & 15);
            c  = ((g == 0) | (g == 3)) ? 0 : 1;
            if (c == 0 && i == jm) mask = 0.f;
            ebase = ee + (((size_t)b * NE + i) * NE + jm) * DF;
        } else {
            int q = ((tk - 32) << 5) + lane;       // 0..255
            i = q >> 3; jm = q & 7; c = 2;
            ebase = en + (((size_t)b * NE + i) * NA + jm) * DF;
        }

        // load 32-feature edge vector (one 128B line per lane)
        float e[DF];
        const float4* p4 = (const float4*)ebase;
        #pragma unroll
        for (int u = 0; u < 8; u++) {
            float4 v = p4[u];
            e[4*u+0] = v.x; e[4*u+1] = v.y; e[4*u+2] = v.z; e[4*u+3] = v.w;
        }

        #pragma unroll
        for (int l = 0; l < NL; l++) {
            const float* w1  = s + OFF_W1 + ((l*3 + c) << 9);   // 32*16
            const float* b1p = s + OFF_B1 + (l*3 + c) * WH;
            float h1[WH];
            #pragma unroll
            for (int o = 0; o < WH; o++) h1[o] = b1p[o];
            #pragma unroll
            for (int f = 0; f < DF; f++) {
                float ef = e[f];
                const float* wr = w1 + f * WH;
                #pragma unroll
                for (int o = 0; o < WH; o++) h1[o] = fmaf(ef, wr[o], h1[o]);
            }
            #pragma unroll
            for (int o = 0; o < WH; o++) h1[o] = sspf(h1[o]);

            const float* w2  = s + OFF_W2 + ((l*3 + c) << 7);   // 16*8
            const float* b2p = s + OFF_B2 + (l*3 + c) * KD;
            float o2[KD];
            #pragma unroll
            for (int k = 0; k < KD; k++) o2[k] = b2p[k];
            #pragma unroll
            for (int f2 = 0; f2 < WH; f2++) {
                float hf = h1[f2];
                const float* wr = w2 + f2 * KD;
                #pragma unroll
                for (int k = 0; k < KD; k++) o2[k] = fmaf(hf, wr[k], o2[k]);
            }
            #pragma unroll
            for (int k = 0; k < KD; k++) o2[k] = sspf(o2[k]);

            if (!isnuc) {
                float* dst = s + OFF_WF + ((((l*NE + i) * NE) + jm) << 3);
                #pragma unroll
                for (int k = 0; k < KD; k++) dst[k] = o2[k] * mask;
            } else {
                float* zn = s + OFF_ZN + ((l*NE + i) << 3);
                const float* yr = s + OFF_Y + jm * KD;
                #pragma unroll
                for (int k = 0; k < KD; k++) atomicAdd(&zn[k], o2[k] * yr[k]);
            }
        }
    }
    __syncthreads();

    // ================= Phase 2: message passing =================
    // init x[i][e] = X_emb[spin(i)][e]
    for (int t = tid; t < NE*ED; t += 256) {
        int i = t >> 4, ei = t & 15;
        s[OFF_X + t] = s[OFF_XE + ((i >= NUP) ? ED : 0) + ei];
    }
    __syncthreads();

    for (int l = 0; l < NL; l++) {
        // hx[j][k] = ssp(x[j] @ hW[l] + hb[l])   (256 outputs, one per thread)
        {
            int j = tid >> 3, k = tid & 7;
            float a = s[OFF_HB + l*KD + k];
            #pragma unroll
            for (int ei = 0; ei < ED; ei++)
                a = fmaf(s[OFF_X + j*ED + ei], s[OFF_HW + (l*ED + ei)*KD + k], a);
            s[OFF_HX + tid] = sspf(a);   // tid == j*8+k
        }
        __syncthreads();
        // z[i][k] = z_nuc + sum_j Wf[l][i][j][k]*hx[j][k]
        {
            int i = tid >> 3, k = tid & 7;
            float a = s[OFF_ZN + (l*NE + i)*KD + k];
            const float* wf = s + OFF_WF + (((l*NE + i) * NE) << 3) + k;
            #pragma unroll
            for (int j = 0; j < NE; j++)
                a = fmaf(wf[j*KD], s[OFF_HX + j*KD + k], a);
            s[OFF_Z + tid] = a;
        }
        __syncthreads();
        // x[i][e] += z[i] @ gW[l] + gb[l]
        for (int t = tid; t < NE*ED; t += 256) {
            int i = t >> 4, ei = t & 15;
            float a = s[OFF_GB + l*ED + ei];
            #pragma unroll
            for (int k = 0; k < KD; k++)
                a = fmaf(s[OFF_Z + i*KD + k], s[OFF_GW + (l*KD + k)*ED + ei], a);
            s[OFF_X + t] += a;
        }
        __syncthreads();
    }

    // readout: out[b] = sum_{i,e} x[i][e]*orbW[e]
    float part = 0.f;
    for (int t = tid; t < NE*ED; t += 256)
        part += s[OFF_X + t] * s[OFF_ORB + (t & 15)];
    #pragma unroll
    for (int off = 16; off > 0; off >>= 1)
        part += __shfl_down_sync(0xffffffffu, part, off);
    if (lane == 0) atomicAdd(&s[OFF_RED], part);
    __syncthreads();
    if (tid == 0) out[b] = s[OFF_RED];
}

extern "C" void kernel_launch(void* const* d_in, const int* in_sizes, int n_in,
                              void* d_out, int out_size) {
    const float* ee   = (const float*)d_in[0];
    const float* en   = (const float*)d_in[1];
    const float* Xemb = (const float*)d_in[2];
    const float* Yv   = (const float*)d_in[3];
    const float* wW1  = (const float*)d_in[4];
    const float* wb1  = (const float*)d_in[5];
    const float* wW2  = (const float*)d_in[6];
    const float* wb2  = (const float*)d_in[7];
    const float* hW   = (const float*)d_in[8];
    const float* hb   = (const float*)d_in[9];
    const float* gW   = (const float*)d_in[10];
    const float* gb   = (const float*)d_in[11];
    const float* orbW = (const float*)d_in[12];
    float* out = (float*)d_out;

    size_t smem = SMEM_FLOATS * sizeof(float);
    cudaFuncSetAttribute(jastrow_kernel,
                         cudaFuncAttributeMaxDynamicSharedMemorySize, (int)smem);
    jastrow_kernel<<<BATCH, 256, smem>>>(ee, en, Xemb, Yv, wW1, wb1, wW2, wb2,
                                         hW, hb, gW, gb, orbW, out);
}